// round 1
// baseline (speedup 1.0000x reference)
#include <cuda_runtime.h>
#include <math.h>

#define BBATCH 2
#define SEQ    2048
#define DMODEL 1024
#define NH     16
#define DH     64
#define MTOT   (BBATCH*SEQ)   // 4096

// ---------------- scratch (static device memory; no allocations) -------------
__device__ float g_q   [(size_t)MTOT*DMODEL];
__device__ float g_k   [(size_t)MTOT*DMODEL];
__device__ float g_v   [(size_t)MTOT*DMODEL];
__device__ float g_attn[(size_t)MTOT*DMODEL];
__device__ float g_dw  [(size_t)MTOT*DMODEL];
__device__ float g_fused[(size_t)MTOT*2*DMODEL];
__device__ float g_scores[(size_t)BBATCH*NH*SEQ*SEQ];   // 512 MB

// ---------------- generic tiled SGEMM ---------------------------------------
// C[m,n] = alpha * sum_k A[m,k] * B(k,n)  (+bias[n]) (+exact GELU)
// BT=true : B is [N,K] row-major (weights, and K matrix for scores)
// BT=false: B is [K,N] row-major (V matrix for PV)
// z-dim batching: offsets = zb*s?b + zh*s?h with zb=z/16, zh=z%16.
template<int BM,int BN,int BK,int TM,int TN,bool BT,bool GELU>
__global__ __launch_bounds__(256)
void gemm_k(const float* __restrict__ A, const float* __restrict__ Bp,
            const float* __restrict__ bias, float* __restrict__ C,
            int K, int lda, int ldb, int ldc, float alpha,
            long sAb, long sAh, long sBb, long sBh, long sCb, long sCh)
{
    const int z  = blockIdx.z;
    const long zb = z >> 4, zh = z & 15;
    A  += zb*sAb + zh*sAh;
    Bp += zb*sBb + zh*sBh;
    C  += zb*sCb + zh*sCh;

    __shared__ float As[BK][BM];
    __shared__ float Bs[BK][BN];

    const int tid = threadIdx.x;
    const int m0  = blockIdx.y * BM;
    const int n0  = blockIdx.x * BN;
    constexpr int TX = BN / TN;
    const int tx = tid % TX;
    const int ty = tid / TX;

    float acc[TM][TN];
    #pragma unroll
    for (int i = 0; i < TM; i++)
        #pragma unroll
        for (int j = 0; j < TN; j++) acc[i][j] = 0.f;

    for (int kt = 0; kt < K; kt += BK) {
        // ---- load A tile (row-major, K-contiguous), transpose into As[k][m]
        {
            constexpr int A4 = BM*BK/4;            // float4 count
            #pragma unroll
            for (int r = 0; r < A4/256; r++) {
                int idx = tid + r*256;
                int m  = idx / (BK/4);
                int k4 = idx % (BK/4);
                float4 vv = *(const float4*)(A + (long)(m0+m)*lda + kt + k4*4);
                As[k4*4+0][m] = vv.x; As[k4*4+1][m] = vv.y;
                As[k4*4+2][m] = vv.z; As[k4*4+3][m] = vv.w;
            }
        }
        // ---- load B tile
        if (BT) {
            constexpr int B4 = BN*BK/4;
            #pragma unroll
            for (int r = 0; r < B4/256; r++) {
                int idx = tid + r*256;
                int n  = idx / (BK/4);
                int k4 = idx % (BK/4);
                float4 vv = *(const float4*)(Bp + (long)(n0+n)*ldb + kt + k4*4);
                Bs[k4*4+0][n] = vv.x; Bs[k4*4+1][n] = vv.y;
                Bs[k4*4+2][n] = vv.z; Bs[k4*4+3][n] = vv.w;
            }
        } else {
            constexpr int B4 = BK*BN/4;
            #pragma unroll
            for (int r = 0; r < B4/256; r++) {
                int idx = tid + r*256;
                int k  = idx / (BN/4);
                int n4 = idx % (BN/4);
                float4 vv = *(const float4*)(Bp + (long)(kt+k)*ldb + n0 + n4*4);
                *(float4*)&Bs[k][n4*4] = vv;
            }
        }
        __syncthreads();

        #pragma unroll
        for (int k = 0; k < BK; k++) {
            float a[TM], b[TN];
            #pragma unroll
            for (int i = 0; i < TM; i++) a[i] = As[k][ty*TM + i];
            #pragma unroll
            for (int j = 0; j < TN; j++) b[j] = Bs[k][tx*TN + j];
            #pragma unroll
            for (int i = 0; i < TM; i++)
                #pragma unroll
                for (int j = 0; j < TN; j++)
                    acc[i][j] += a[i]*b[j];
        }
        __syncthreads();
    }

    // ---- epilogue: scale, bias, (gelu), vectorized store
    #pragma unroll
    for (int i = 0; i < TM; i++) {
        const int m = m0 + ty*TM + i;
        #pragma unroll
        for (int j4 = 0; j4 < TN/4; j4++) {
            const int n = n0 + tx*TN + j4*4;
            float4 vv;
            float* vp = &vv.x;
            #pragma unroll
            for (int j = 0; j < 4; j++) {
                float t = acc[i][j4*4+j] * alpha;
                if (bias) t += bias[n + j];
                if (GELU) t = 0.5f * t * (1.f + erff(t * 0.70710678118654752f));
                vp[j] = t;
            }
            *(float4*)(C + (long)m*ldc + n) = vv;
        }
    }
}

// ---------------- depthwise conv (K=3, pad=1) --------------------------------
__global__ __launch_bounds__(256)
void dwconv_k(const float* __restrict__ x, const float* __restrict__ w,
              const float* __restrict__ b, float* __restrict__ out)
{
    long i = (long)blockIdx.x*256 + threadIdx.x;      // over MTOT*DMODEL
    int  c  = (int)(i & (DMODEL-1));
    long sl = i >> 10;                                 // b*SEQ + s
    int  s  = (int)(sl & (SEQ-1));
    float w0 = w[c*3+0], w1 = w[c*3+1], w2 = w[c*3+2];
    float acc = b[c] + w1 * x[i];
    if (s > 0)      acc += w0 * x[i - DMODEL];
    if (s < SEQ-1)  acc += w2 * x[i + DMODEL];
    out[i] = acc;
}

// ---------------- row softmax over SEQ=2048 ----------------------------------
__global__ __launch_bounds__(256)
void softmax_k(float* __restrict__ S)
{
    long row = blockIdx.x;
    float* p = S + row * (long)SEQ;
    const int t = threadIdx.x;

    float4 v0 = ((float4*)p)[t];
    float4 v1 = ((float4*)p)[t + 256];

    float mx = fmaxf(fmaxf(fmaxf(v0.x,v0.y), fmaxf(v0.z,v0.w)),
                     fmaxf(fmaxf(v1.x,v1.y), fmaxf(v1.z,v1.w)));
    __shared__ float red[8];
    #pragma unroll
    for (int o = 16; o > 0; o >>= 1) mx = fmaxf(mx, __shfl_xor_sync(~0u, mx, o));
    if ((t & 31) == 0) red[t >> 5] = mx;
    __syncthreads();
    if (t < 8) {
        float m = red[t];
        #pragma unroll
        for (int o = 4; o > 0; o >>= 1) m = fmaxf(m, __shfl_xor_sync(0xff, m, o));
        if (t == 0) red[0] = m;
    }
    __syncthreads();
    mx = red[0];
    __syncthreads();

    v0.x = expf(v0.x-mx); v0.y = expf(v0.y-mx); v0.z = expf(v0.z-mx); v0.w = expf(v0.w-mx);
    v1.x = expf(v1.x-mx); v1.y = expf(v1.y-mx); v1.z = expf(v1.z-mx); v1.w = expf(v1.w-mx);
    float sum = v0.x+v0.y+v0.z+v0.w + v1.x+v1.y+v1.z+v1.w;
    #pragma unroll
    for (int o = 16; o > 0; o >>= 1) sum += __shfl_xor_sync(~0u, sum, o);
    if ((t & 31) == 0) red[t >> 5] = sum;
    __syncthreads();
    if (t < 8) {
        float s = red[t];
        #pragma unroll
        for (int o = 4; o > 0; o >>= 1) s += __shfl_xor_sync(0xff, s, o);
        if (t == 0) red[0] = s;
    }
    __syncthreads();
    float inv = 1.f / red[0];

    v0.x*=inv; v0.y*=inv; v0.z*=inv; v0.w*=inv;
    v1.x*=inv; v1.y*=inv; v1.z*=inv; v1.w*=inv;
    ((float4*)p)[t]       = v0;
    ((float4*)p)[t + 256] = v1;
}

// ---------------- launcher ----------------------------------------------------
extern "C" void kernel_launch(void* const* d_in, const int* in_sizes, int n_in,
                              void* d_out, int out_size)
{
    const float* x    = (const float*)d_in[0];
    const float* wq   = (const float*)d_in[1];
    const float* bq   = (const float*)d_in[2];
    const float* wk   = (const float*)d_in[3];
    const float* bk   = (const float*)d_in[4];
    const float* wv   = (const float*)d_in[5];
    const float* bv   = (const float*)d_in[6];
    const float* wo   = (const float*)d_in[7];
    const float* bo   = (const float*)d_in[8];
    const float* dw_w = (const float*)d_in[9];
    const float* dw_b = (const float*)d_in[10];
    const float* pw_w = (const float*)d_in[11];
    const float* pw_b = (const float*)d_in[12];
    const float* fu_w = (const float*)d_in[13];
    const float* fu_b = (const float*)d_in[14];
    float* out = (float*)d_out;

    float *q,*k,*v,*attn,*dw,*fused,*scores;
    cudaGetSymbolAddress((void**)&q,      g_q);
    cudaGetSymbolAddress((void**)&k,      g_k);
    cudaGetSymbolAddress((void**)&v,      g_v);
    cudaGetSymbolAddress((void**)&attn,   g_attn);
    cudaGetSymbolAddress((void**)&dw,     g_dw);
    cudaGetSymbolAddress((void**)&fused,  g_fused);
    cudaGetSymbolAddress((void**)&scores, g_scores);

    const dim3 thr(256);
    const dim3 gProj(DMODEL/128, MTOT/128, 1);         // 8 x 32

    // Q/K/V projections: [4096,1024] = x[4096,1024] @ W^T + b
    gemm_k<128,128,16,8,8,true,false><<<gProj,thr>>>(x, wq, bq, q,
        DMODEL, DMODEL, DMODEL, DMODEL, 1.f, 0,0,0,0,0,0);
    gemm_k<128,128,16,8,8,true,false><<<gProj,thr>>>(x, wk, bk, k,
        DMODEL, DMODEL, DMODEL, DMODEL, 1.f, 0,0,0,0,0,0);
    gemm_k<128,128,16,8,8,true,false><<<gProj,thr>>>(x, wv, bv, v,
        DMODEL, DMODEL, DMODEL, DMODEL, 1.f, 0,0,0,0,0,0);

    // depthwise conv branch
    dwconv_k<<<(MTOT*DMODEL)/256, thr>>>(x, dw_w, dw_b, dw);
    // pointwise + exact GELU -> right half of fused buffer
    gemm_k<128,128,16,8,8,true,true><<<gProj,thr>>>(dw, pw_w, pw_b, fused + DMODEL,
        DMODEL, DMODEL, DMODEL, 2*DMODEL, 1.f, 0,0,0,0,0,0);

    // attention scores: per (b,h): S = Q K^T / 8
    const dim3 gS(SEQ/128, SEQ/128, BBATCH*NH);        // 16 x 16 x 32
    gemm_k<128,128,16,8,8,true,false><<<gS,thr>>>(q, k, nullptr, scores,
        DH, DMODEL, DMODEL, SEQ, 0.125f,
        (long)SEQ*DMODEL, 64, (long)SEQ*DMODEL, 64,
        (long)NH*SEQ*SEQ, (long)SEQ*SEQ);

    // softmax in place
    softmax_k<<<BBATCH*NH*SEQ, thr>>>(scores);

    // PV: per (b,h): attn = P V   (write back into [B,S,d] layout)
    const dim3 gPV(DH/64, SEQ/128, BBATCH*NH);         // 1 x 16 x 32
    gemm_k<128,64,16,8,4,false,false><<<gPV,thr>>>(scores, v, nullptr, attn,
        SEQ, SEQ, DMODEL, DMODEL, 1.f,
        (long)NH*SEQ*SEQ, (long)SEQ*SEQ,
        (long)SEQ*DMODEL, 64, (long)SEQ*DMODEL, 64);

    // output projection -> left half of fused buffer
    gemm_k<128,128,16,8,8,true,false><<<gProj,thr>>>(attn, wo, bo, fused,
        DMODEL, DMODEL, DMODEL, 2*DMODEL, 1.f, 0,0,0,0,0,0);

    // fusion: out = fused[4096,2048] @ fu_w^T + fu_b
    gemm_k<128,128,16,8,8,true,false><<<gProj,thr>>>(fused, fu_w, fu_b, out,
        2*DMODEL, 2*DMODEL, 2*DMODEL, DMODEL, 1.f, 0,0,0,0,0,0);
}

// round 2
// speedup vs baseline: 2.1731x; 2.1731x over previous
#include <cuda_runtime.h>
#include <cuda_bf16.h>
#include <math.h>
#include <stdint.h>

#define BBATCH 2
#define SEQ    2048
#define DMODEL 1024
#define NH     16
#define DH     64
#define MTOT   (BBATCH*SEQ)   // 4096

// ---------------- scratch (static device memory; no allocations) -------------
__device__ float g_q   [(size_t)MTOT*DMODEL];
__device__ float g_k   [(size_t)MTOT*DMODEL];
__device__ float g_v   [(size_t)MTOT*DMODEL];
__device__ float g_attn[(size_t)MTOT*DMODEL];
__device__ float g_dw  [(size_t)MTOT*DMODEL];
__device__ float g_fused[(size_t)MTOT*2*DMODEL];
__device__ float g_scores[(size_t)BBATCH*NH*SEQ*SEQ];   // 512 MB

// ---------------- mma helpers -------------------------------------------------
__device__ __forceinline__ void ldsm4(uint32_t* r, uint32_t addr) {
    asm volatile("ldmatrix.sync.aligned.m8n8.x4.shared.b16 {%0,%1,%2,%3}, [%4];\n"
                 : "=r"(r[0]), "=r"(r[1]), "=r"(r[2]), "=r"(r[3]) : "r"(addr));
}
__device__ __forceinline__ void mma16816(float* c, const uint32_t* a, const uint32_t* b) {
    asm volatile("mma.sync.aligned.m16n8k16.row.col.f32.bf16.bf16.f32 "
                 "{%0,%1,%2,%3},{%4,%5,%6,%7},{%8,%9},{%0,%1,%2,%3};\n"
                 : "+f"(c[0]), "+f"(c[1]), "+f"(c[2]), "+f"(c[3])
                 : "r"(a[0]), "r"(a[1]), "r"(a[2]), "r"(a[3]), "r"(b[0]), "r"(b[1]));
}
__device__ __forceinline__ uint32_t pack2(__nv_bfloat16 a, __nv_bfloat16 b) {
    __nv_bfloat162 t; t.x = a; t.y = b;
    return *reinterpret_cast<uint32_t*>(&t);
}
__device__ __forceinline__ void split2(float x, __nv_bfloat16& h, __nv_bfloat16& l) {
    h = __float2bfloat16_rn(x);
    l = __float2bfloat16_rn(x - __bfloat162float(h));
}

// ---------------- bf16x3 tensor-core GEMM ------------------------------------
// C[m,n] = alpha * sum_k A[m,k]*B(k,n) (+bias) (+exact GELU)
// BT=true : B is [N,K] row-major;  BT=false: B is [K,N] row-major
// z-batching: zb=z/16, zh=z%16 offsets.
template<int BM, int BN, int WM, int WN, bool BT, bool GELU>
__global__ __launch_bounds__(256, 2)
void mma_gemm(const float* __restrict__ A, const float* __restrict__ Bp,
              const float* __restrict__ bias, float* __restrict__ C,
              int K, int lda, int ldb, int ldc, float alpha,
              long sAb, long sAh, long sBb, long sBh, long sCb, long sCh)
{
    constexpr int BK  = 32;
    constexpr int BKP = 40;                 // padded row: 80B, conflict-free ldmatrix
    constexpr int MT  = BM / (WM * 16);     // m-tiles (16) per warp
    constexpr int NT  = BN / (WN * 8);      // n-tiles (8)  per warp

    const int z  = blockIdx.z;
    const long zb = z >> 4, zh = z & 15;
    A  += zb * sAb + zh * sAh;
    Bp += zb * sBb + zh * sBh;
    C  += zb * sCb + zh * sCh;

    __shared__ __nv_bfloat16 Ah[BM][BKP], Al[BM][BKP];
    __shared__ __nv_bfloat16 Bh[BN][BKP], Bl[BN][BKP];

    const int tid  = threadIdx.x;
    const int warp = tid >> 5;
    const int lane = tid & 31;
    const int wm   = warp % WM;
    const int wn   = warp / WM;
    const int m0   = blockIdx.y * BM;
    const int n0   = blockIdx.x * BN;

    float acc[MT][NT][4];
    #pragma unroll
    for (int i = 0; i < MT; i++)
        #pragma unroll
        for (int j = 0; j < NT; j++)
            #pragma unroll
            for (int r = 0; r < 4; r++) acc[i][j][r] = 0.f;

    const uint32_t sAh_b = (uint32_t)__cvta_generic_to_shared(&Ah[0][0]);
    const uint32_t sAl_b = (uint32_t)__cvta_generic_to_shared(&Al[0][0]);
    const uint32_t sBh_b = (uint32_t)__cvta_generic_to_shared(&Bh[0][0]);
    const uint32_t sBl_b = (uint32_t)__cvta_generic_to_shared(&Bl[0][0]);

    // ldmatrix per-lane address components
    const int a_row = wm * (MT * 16) + ((lane >> 3) & 1) * 8 + (lane & 7);
    const int a_k   = (lane >> 4) * 8;
    const int b_row = wn * (NT * 8) + (lane >> 4) * 8 + (lane & 7);
    const int b_k   = ((lane >> 3) & 1) * 8;

    for (int kt = 0; kt < K; kt += BK) {
        // ---- A tile: fp32 load + hi/lo split
        #pragma unroll
        for (int r = 0; r < BM * BK / (256 * 4); r++) {
            int idx = tid + r * 256;
            int m   = idx >> 3;           // /(BK/4)
            int k4  = idx & 7;
            float4 vv = *(const float4*)(A + (long)(m0 + m) * lda + kt + k4 * 4);
            __nv_bfloat16 h0,h1,h2,h3,l0,l1,l2,l3;
            split2(vv.x,h0,l0); split2(vv.y,h1,l1); split2(vv.z,h2,l2); split2(vv.w,h3,l3);
            *(uint2*)&Ah[m][k4*4] = make_uint2(pack2(h0,h1), pack2(h2,h3));
            *(uint2*)&Al[m][k4*4] = make_uint2(pack2(l0,l1), pack2(l2,l3));
        }
        // ---- B tile
        if (BT) {
            #pragma unroll
            for (int r = 0; r < BN * BK / (256 * 4); r++) {
                int idx = tid + r * 256;
                int n   = idx >> 3;
                int k4  = idx & 7;
                float4 vv = *(const float4*)(Bp + (long)(n0 + n) * ldb + kt + k4 * 4);
                __nv_bfloat16 h0,h1,h2,h3,l0,l1,l2,l3;
                split2(vv.x,h0,l0); split2(vv.y,h1,l1); split2(vv.z,h2,l2); split2(vv.w,h3,l3);
                *(uint2*)&Bh[n][k4*4] = make_uint2(pack2(h0,h1), pack2(h2,h3));
                *(uint2*)&Bl[n][k4*4] = make_uint2(pack2(l0,l1), pack2(l2,l3));
            }
        } else {
            #pragma unroll
            for (int r = 0; r < BK * BN / (256 * 4); r++) {
                int idx = tid + r * 256;
                int k   = idx / (BN / 4);
                int n4  = idx % (BN / 4);
                float4 vv = *(const float4*)(Bp + (long)(kt + k) * ldb + n0 + n4 * 4);
                const float* vp = &vv.x;
                #pragma unroll
                for (int j = 0; j < 4; j++) {
                    __nv_bfloat16 h, l;
                    split2(vp[j], h, l);
                    Bh[n4*4 + j][k] = h;
                    Bl[n4*4 + j][k] = l;
                }
            }
        }
        __syncthreads();

        #pragma unroll
        for (int k16 = 0; k16 < BK; k16 += 16) {
            uint32_t afh[MT][4], afl[MT][4], bfh[NT][2], bfl[NT][2];
            // A-hi frags
            #pragma unroll
            for (int mt = 0; mt < MT; mt++)
                ldsm4(afh[mt], sAh_b + ((a_row + mt*16) * BKP + a_k + k16) * 2);
            // B-hi frags (x4 covers 2 n-tiles)
            #pragma unroll
            for (int t = 0; t < NT / 2; t++) {
                uint32_t rr[4];
                ldsm4(rr, sBh_b + ((b_row + t*16) * BKP + b_k + k16) * 2);
                bfh[2*t][0] = rr[0]; bfh[2*t][1] = rr[1];
                bfh[2*t+1][0] = rr[2]; bfh[2*t+1][1] = rr[3];
            }
            // pass 1: hi*hi
            #pragma unroll
            for (int mt = 0; mt < MT; mt++)
                #pragma unroll
                for (int nt = 0; nt < NT; nt++)
                    mma16816(acc[mt][nt], afh[mt], bfh[nt]);
            // B-lo frags
            #pragma unroll
            for (int t = 0; t < NT / 2; t++) {
                uint32_t rr[4];
                ldsm4(rr, sBl_b + ((b_row + t*16) * BKP + b_k + k16) * 2);
                bfl[2*t][0] = rr[0]; bfl[2*t][1] = rr[1];
                bfl[2*t+1][0] = rr[2]; bfl[2*t+1][1] = rr[3];
            }
            // pass 2: hi*lo
            #pragma unroll
            for (int mt = 0; mt < MT; mt++)
                #pragma unroll
                for (int nt = 0; nt < NT; nt++)
                    mma16816(acc[mt][nt], afh[mt], bfl[nt]);
            // A-lo frags
            #pragma unroll
            for (int mt = 0; mt < MT; mt++)
                ldsm4(afl[mt], sAl_b + ((a_row + mt*16) * BKP + a_k + k16) * 2);
            // pass 3: lo*hi
            #pragma unroll
            for (int mt = 0; mt < MT; mt++)
                #pragma unroll
                for (int nt = 0; nt < NT; nt++)
                    mma16816(acc[mt][nt], afl[mt], bfh[nt]);
        }
        __syncthreads();
    }

    // ---- epilogue
    #pragma unroll
    for (int mt = 0; mt < MT; mt++) {
        #pragma unroll
        for (int nt = 0; nt < NT; nt++) {
            const int row0 = m0 + wm * (MT * 16) + mt * 16 + (lane >> 2);
            const int col  = n0 + wn * (NT * 8)  + nt * 8  + (lane & 3) * 2;
            float b0 = 0.f, b1 = 0.f;
            if (bias) { b0 = bias[col]; b1 = bias[col + 1]; }
            #pragma unroll
            for (int half = 0; half < 2; half++) {
                const int row = row0 + half * 8;
                float t0 = acc[mt][nt][half*2 + 0] * alpha + b0;
                float t1 = acc[mt][nt][half*2 + 1] * alpha + b1;
                if (GELU) {
                    t0 = 0.5f * t0 * (1.f + erff(t0 * 0.70710678118654752f));
                    t1 = 0.5f * t1 * (1.f + erff(t1 * 0.70710678118654752f));
                }
                *(float2*)(C + (long)row * ldc + col) = make_float2(t0, t1);
            }
        }
    }
}

// ---------------- depthwise conv (K=3, pad=1) --------------------------------
__global__ __launch_bounds__(256)
void dwconv_k(const float* __restrict__ x, const float* __restrict__ w,
              const float* __restrict__ b, float* __restrict__ out)
{
    long i = (long)blockIdx.x*256 + threadIdx.x;
    int  c  = (int)(i & (DMODEL-1));
    long sl = i >> 10;
    int  s  = (int)(sl & (SEQ-1));
    float w0 = w[c*3+0], w1 = w[c*3+1], w2 = w[c*3+2];
    float acc = b[c] + w1 * x[i];
    if (s > 0)      acc += w0 * x[i - DMODEL];
    if (s < SEQ-1)  acc += w2 * x[i + DMODEL];
    out[i] = acc;
}

// ---------------- row softmax over SEQ=2048 ----------------------------------
__global__ __launch_bounds__(256)
void softmax_k(float* __restrict__ S)
{
    long row = blockIdx.x;
    float* p = S + row * (long)SEQ;
    const int t = threadIdx.x;

    float4 v0 = ((float4*)p)[t];
    float4 v1 = ((float4*)p)[t + 256];

    float mx = fmaxf(fmaxf(fmaxf(v0.x,v0.y), fmaxf(v0.z,v0.w)),
                     fmaxf(fmaxf(v1.x,v1.y), fmaxf(v1.z,v1.w)));
    __shared__ float red[8];
    #pragma unroll
    for (int o = 16; o > 0; o >>= 1) mx = fmaxf(mx, __shfl_xor_sync(~0u, mx, o));
    if ((t & 31) == 0) red[t >> 5] = mx;
    __syncthreads();
    if (t < 8) {
        float m = red[t];
        #pragma unroll
        for (int o = 4; o > 0; o >>= 1) m = fmaxf(m, __shfl_xor_sync(0xff, m, o));
        if (t == 0) red[0] = m;
    }
    __syncthreads();
    mx = red[0];
    __syncthreads();

    v0.x = expf(v0.x-mx); v0.y = expf(v0.y-mx); v0.z = expf(v0.z-mx); v0.w = expf(v0.w-mx);
    v1.x = expf(v1.x-mx); v1.y = expf(v1.y-mx); v1.z = expf(v1.z-mx); v1.w = expf(v1.w-mx);
    float sum = v0.x+v0.y+v0.z+v0.w + v1.x+v1.y+v1.z+v1.w;
    #pragma unroll
    for (int o = 16; o > 0; o >>= 1) sum += __shfl_xor_sync(~0u, sum, o);
    if ((t & 31) == 0) red[t >> 5] = sum;
    __syncthreads();
    if (t < 8) {
        float s = red[t];
        #pragma unroll
        for (int o = 4; o > 0; o >>= 1) s += __shfl_xor_sync(0xff, s, o);
        if (t == 0) red[0] = s;
    }
    __syncthreads();
    float inv = 1.f / red[0];

    v0.x*=inv; v0.y*=inv; v0.z*=inv; v0.w*=inv;
    v1.x*=inv; v1.y*=inv; v1.z*=inv; v1.w*=inv;
    ((float4*)p)[t]       = v0;
    ((float4*)p)[t + 256] = v1;
}

// ---------------- launcher ----------------------------------------------------
extern "C" void kernel_launch(void* const* d_in, const int* in_sizes, int n_in,
                              void* d_out, int out_size)
{
    const float* x    = (const float*)d_in[0];
    const float* wq   = (const float*)d_in[1];
    const float* bq   = (const float*)d_in[2];
    const float* wk   = (const float*)d_in[3];
    const float* bk   = (const float*)d_in[4];
    const float* wv   = (const float*)d_in[5];
    const float* bv   = (const float*)d_in[6];
    const float* wo   = (const float*)d_in[7];
    const float* bo   = (const float*)d_in[8];
    const float* dw_w = (const float*)d_in[9];
    const float* dw_b = (const float*)d_in[10];
    const float* pw_w = (const float*)d_in[11];
    const float* pw_b = (const float*)d_in[12];
    const float* fu_w = (const float*)d_in[13];
    const float* fu_b = (const float*)d_in[14];
    float* out = (float*)d_out;

    float *q,*k,*v,*attn,*dw,*fused,*scores;
    cudaGetSymbolAddress((void**)&q,      g_q);
    cudaGetSymbolAddress((void**)&k,      g_k);
    cudaGetSymbolAddress((void**)&v,      g_v);
    cudaGetSymbolAddress((void**)&attn,   g_attn);
    cudaGetSymbolAddress((void**)&dw,     g_dw);
    cudaGetSymbolAddress((void**)&fused,  g_fused);
    cudaGetSymbolAddress((void**)&scores, g_scores);

    const dim3 thr(256);
    const dim3 gProj(DMODEL/128, MTOT/128, 1);         // 8 x 32

    // Q/K/V projections
    mma_gemm<128,128,2,4,true,false><<<gProj,thr>>>(x, wq, bq, q,
        DMODEL, DMODEL, DMODEL, DMODEL, 1.f, 0,0,0,0,0,0);
    mma_gemm<128,128,2,4,true,false><<<gProj,thr>>>(x, wk, bk, k,
        DMODEL, DMODEL, DMODEL, DMODEL, 1.f, 0,0,0,0,0,0);
    mma_gemm<128,128,2,4,true,false><<<gProj,thr>>>(x, wv, bv, v,
        DMODEL, DMODEL, DMODEL, DMODEL, 1.f, 0,0,0,0,0,0);

    // conv branch
    dwconv_k<<<(MTOT*DMODEL)/256, thr>>>(x, dw_w, dw_b, dw);
    mma_gemm<128,128,2,4,true,true><<<gProj,thr>>>(dw, pw_w, pw_b, fused + DMODEL,
        DMODEL, DMODEL, DMODEL, 2*DMODEL, 1.f, 0,0,0,0,0,0);

    // attention scores: per (b,h): S = Q K^T / 8
    const dim3 gS(SEQ/128, SEQ/128, BBATCH*NH);
    mma_gemm<128,128,2,4,true,false><<<gS,thr>>>(q, k, nullptr, scores,
        DH, DMODEL, DMODEL, SEQ, 0.125f,
        (long)SEQ*DMODEL, 64, (long)SEQ*DMODEL, 64,
        (long)NH*SEQ*SEQ, (long)SEQ*SEQ);

    softmax_k<<<BBATCH*NH*SEQ, thr>>>(scores);

    // PV: per (b,h): attn = P V
    const dim3 gPV(DH/64, SEQ/128, BBATCH*NH);
    mma_gemm<128,64,4,2,false,false><<<gPV,thr>>>(scores, v, nullptr, attn,
        SEQ, SEQ, DMODEL, DMODEL, 1.f,
        (long)NH*SEQ*SEQ, (long)SEQ*SEQ,
        (long)SEQ*DMODEL, 64, (long)SEQ*DMODEL, 64);

    // output projection
    mma_gemm<128,128,2,4,true,false><<<gProj,thr>>>(attn, wo, bo, fused,
        DMODEL, DMODEL, DMODEL, 2*DMODEL, 1.f, 0,0,0,0,0,0);

    // fusion
    mma_gemm<128,128,2,4,true,false><<<gProj,thr>>>(fused, fu_w, fu_b, out,
        2*DMODEL, 2*DMODEL, 2*DMODEL, DMODEL, 1.f, 0,0,0,0,0,0);
}

// round 3
// speedup vs baseline: 2.6804x; 1.2334x over previous
#include <cuda_runtime.h>
#include <cuda_bf16.h>
#include <math.h>
#include <stdint.h>

#define BBATCH 2
#define SEQ    2048
#define DMODEL 1024
#define NH     16
#define DH     64
#define MTOT   (BBATCH*SEQ)   // 4096

// ---------------- scratch (static device memory; no allocations) -------------
__device__ float g_q   [(size_t)MTOT*DMODEL];
__device__ float g_k   [(size_t)MTOT*DMODEL];
__device__ float g_v   [(size_t)MTOT*DMODEL];
__device__ float g_attn[(size_t)MTOT*DMODEL];
__device__ float g_dw  [(size_t)MTOT*DMODEL];
__device__ float g_fused[(size_t)MTOT*2*DMODEL];

// ---------------- helpers -----------------------------------------------------
__device__ __forceinline__ void ldsm4(uint32_t* r, uint32_t addr) {
    asm volatile("ldmatrix.sync.aligned.m8n8.x4.shared.b16 {%0,%1,%2,%3}, [%4];\n"
                 : "=r"(r[0]), "=r"(r[1]), "=r"(r[2]), "=r"(r[3]) : "r"(addr));
}
__device__ __forceinline__ void mma16816(float* c, const uint32_t* a, const uint32_t* b) {
    asm volatile("mma.sync.aligned.m16n8k16.row.col.f32.bf16.bf16.f32 "
                 "{%0,%1,%2,%3},{%4,%5,%6,%7},{%8,%9},{%0,%1,%2,%3};\n"
                 : "+f"(c[0]), "+f"(c[1]), "+f"(c[2]), "+f"(c[3])
                 : "r"(a[0]), "r"(a[1]), "r"(a[2]), "r"(a[3]), "r"(b[0]), "r"(b[1]));
}
__device__ __forceinline__ uint32_t pack2(__nv_bfloat16 a, __nv_bfloat16 b) {
    __nv_bfloat162 t; t.x = a; t.y = b;
    return *reinterpret_cast<uint32_t*>(&t);
}
__device__ __forceinline__ void split2(float x, __nv_bfloat16& h, __nv_bfloat16& l) {
    h = __float2bfloat16_rn(x);
    l = __float2bfloat16_rn(x - __bfloat162float(h));
}
// exp2 on FMA pipe only (no MUFU). Valid for t <= 0 (clamped at -120).
__device__ __forceinline__ float exp2f_fast(float t) {
    t = fmaxf(t, -120.0f);
    float z = t + 12582912.0f;                       // 1.5*2^23: round-to-int
    int   n = __float_as_int(z) - 0x4B400000;        // integer part
    float f = t - (z - 12582912.0f);                 // frac in [-0.5, 0.5]
    float p =             0.0018775767f;
    p = fmaf(p, f, 0.0089893397f);
    p = fmaf(p, f, 0.0558015586f);
    p = fmaf(p, f, 0.2401596780f);
    p = fmaf(p, f, 0.6931471805f);
    p = fmaf(p, f, 1.0000000000f);
    return __int_as_float(__float_as_int(p) + (n << 23));
}

// ---------------- dense bf16x3 tensor-core GEMM body --------------------------
// C[m,n] = sum_k A[m,k] * B[n,k] + bias[n]  (optional exact GELU)
// Fixed tile: BM=BN=128, BK=32, 8 warps (2x4), MT=NT=4.
__device__ __forceinline__ void dense_body(
    const float* __restrict__ A, const float* __restrict__ Bp,
    const float* __restrict__ bias, float* __restrict__ C,
    int K, int lda, int ldb, int ldc, bool gelu)
{
    constexpr int BKP = 40;
    __shared__ __nv_bfloat16 Ah[128][BKP], Al[128][BKP];
    __shared__ __nv_bfloat16 Bh[128][BKP], Bl[128][BKP];

    const int tid  = threadIdx.x;
    const int warp = tid >> 5;
    const int lane = tid & 31;
    const int wm   = warp & 1;        // WM=2
    const int wn   = warp >> 1;       // WN=4
    const int m0   = blockIdx.y * 128;
    const int n0   = blockIdx.x * 128;

    float acc[4][4][4];
    #pragma unroll
    for (int i = 0; i < 4; i++)
        #pragma unroll
        for (int j = 0; j < 4; j++)
            #pragma unroll
            for (int r = 0; r < 4; r++) acc[i][j][r] = 0.f;

    const uint32_t sAh_b = (uint32_t)__cvta_generic_to_shared(&Ah[0][0]);
    const uint32_t sAl_b = (uint32_t)__cvta_generic_to_shared(&Al[0][0]);
    const uint32_t sBh_b = (uint32_t)__cvta_generic_to_shared(&Bh[0][0]);
    const uint32_t sBl_b = (uint32_t)__cvta_generic_to_shared(&Bl[0][0]);

    const int a_row = wm * 64 + ((lane >> 3) & 1) * 8 + (lane & 7);
    const int a_k   = (lane >> 4) * 8;
    const int b_row = wn * 32 + (lane >> 4) * 8 + (lane & 7);
    const int b_k   = ((lane >> 3) & 1) * 8;

    for (int kt = 0; kt < K; kt += 32) {
        #pragma unroll
        for (int r = 0; r < 4; r++) {
            int idx = tid + r * 256;
            int m   = idx >> 3;
            int k4  = idx & 7;
            float4 vv = *(const float4*)(A + (long)(m0 + m) * lda + kt + k4 * 4);
            __nv_bfloat16 h0,h1,h2,h3,l0,l1,l2,l3;
            split2(vv.x,h0,l0); split2(vv.y,h1,l1); split2(vv.z,h2,l2); split2(vv.w,h3,l3);
            *(uint2*)&Ah[m][k4*4] = make_uint2(pack2(h0,h1), pack2(h2,h3));
            *(uint2*)&Al[m][k4*4] = make_uint2(pack2(l0,l1), pack2(l2,l3));
        }
        #pragma unroll
        for (int r = 0; r < 4; r++) {
            int idx = tid + r * 256;
            int n   = idx >> 3;
            int k4  = idx & 7;
            float4 vv = *(const float4*)(Bp + (long)(n0 + n) * ldb + kt + k4 * 4);
            __nv_bfloat16 h0,h1,h2,h3,l0,l1,l2,l3;
            split2(vv.x,h0,l0); split2(vv.y,h1,l1); split2(vv.z,h2,l2); split2(vv.w,h3,l3);
            *(uint2*)&Bh[n][k4*4] = make_uint2(pack2(h0,h1), pack2(h2,h3));
            *(uint2*)&Bl[n][k4*4] = make_uint2(pack2(l0,l1), pack2(l2,l3));
        }
        __syncthreads();

        #pragma unroll
        for (int k16 = 0; k16 < 32; k16 += 16) {
            uint32_t afh[4][4], afl[4][4], bfh[4][2], bfl[4][2];
            #pragma unroll
            for (int mt = 0; mt < 4; mt++)
                ldsm4(afh[mt], sAh_b + ((a_row + mt*16) * BKP + a_k + k16) * 2);
            #pragma unroll
            for (int t = 0; t < 2; t++) {
                uint32_t rr[4];
                ldsm4(rr, sBh_b + ((b_row + t*16) * BKP + b_k + k16) * 2);
                bfh[2*t][0] = rr[0]; bfh[2*t][1] = rr[1];
                bfh[2*t+1][0] = rr[2]; bfh[2*t+1][1] = rr[3];
            }
            #pragma unroll
            for (int mt = 0; mt < 4; mt++)
                #pragma unroll
                for (int nt = 0; nt < 4; nt++)
                    mma16816(acc[mt][nt], afh[mt], bfh[nt]);
            #pragma unroll
            for (int t = 0; t < 2; t++) {
                uint32_t rr[4];
                ldsm4(rr, sBl_b + ((b_row + t*16) * BKP + b_k + k16) * 2);
                bfl[2*t][0] = rr[0]; bfl[2*t][1] = rr[1];
                bfl[2*t+1][0] = rr[2]; bfl[2*t+1][1] = rr[3];
            }
            #pragma unroll
            for (int mt = 0; mt < 4; mt++)
                #pragma unroll
                for (int nt = 0; nt < 4; nt++)
                    mma16816(acc[mt][nt], afh[mt], bfl[nt]);
            #pragma unroll
            for (int mt = 0; mt < 4; mt++)
                ldsm4(afl[mt], sAl_b + ((a_row + mt*16) * BKP + a_k + k16) * 2);
            #pragma unroll
            for (int mt = 0; mt < 4; mt++)
                #pragma unroll
                for (int nt = 0; nt < 4; nt++)
                    mma16816(acc[mt][nt], afl[mt], bfh[nt]);
        }
        __syncthreads();
    }

    #pragma unroll
    for (int mt = 0; mt < 4; mt++) {
        #pragma unroll
        for (int nt = 0; nt < 4; nt++) {
            const int row0 = m0 + wm * 64 + mt * 16 + (lane >> 2);
            const int col  = n0 + wn * 32 + nt * 8  + (lane & 3) * 2;
            float b0 = bias ? bias[col] : 0.f;
            float b1 = bias ? bias[col + 1] : 0.f;
            #pragma unroll
            for (int half = 0; half < 2; half++) {
                const int row = row0 + half * 8;
                float t0 = acc[mt][nt][half*2 + 0] + b0;
                float t1 = acc[mt][nt][half*2 + 1] + b1;
                if (gelu) {
                    t0 = 0.5f * t0 * (1.f + erff(t0 * 0.70710678118654752f));
                    t1 = 0.5f * t1 * (1.f + erff(t1 * 0.70710678118654752f));
                }
                *(float2*)(C + (long)row * ldc + col) = make_float2(t0, t1);
            }
        }
    }
}

// wrappers ---------------------------------------------------------------------
__global__ __launch_bounds__(256, 2)
void qkv_gemm(const float* __restrict__ x,
              const float* wq, const float* wk, const float* wv,
              const float* bq, const float* bk, const float* bv,
              float* q, float* k, float* v)
{
    const int z = blockIdx.z;
    const float* W = (z == 0) ? wq : (z == 1) ? wk : wv;
    const float* B = (z == 0) ? bq : (z == 1) ? bk : bv;
    float*       C = (z == 0) ? q  : (z == 1) ? k  : v;
    dense_body(x, W, B, C, DMODEL, DMODEL, DMODEL, DMODEL, false);
}

__global__ __launch_bounds__(256, 2)
void pair_gemm(const float* a0, const float* a1,
               const float* w0, const float* w1,
               const float* b0, const float* b1,
               float* c0, float* c1)
{
    const int z = blockIdx.z;
    dense_body(z == 0 ? a0 : a1, z == 0 ? w0 : w1, z == 0 ? b0 : b1,
               z == 0 ? c0 : c1, DMODEL, DMODEL, DMODEL, 2*DMODEL, z == 0);
}

__global__ __launch_bounds__(256, 2)
void fusion_gemm(const float* __restrict__ A, const float* __restrict__ W,
                 const float* __restrict__ B, float* __restrict__ C)
{
    dense_body(A, W, B, C, 2*DMODEL, 2*DMODEL, 2*DMODEL, DMODEL, false);
}

// ---------------- flash attention ---------------------------------------------
// Per CTA: 128 Q rows for one (b,h); K/V tiles of 64 keys. 8 warps, each warp
// owns 16 Q rows x all keys. Softmax in base-2 domain (Q pre-scaled by log2e/8).
__global__ __launch_bounds__(256, 2)
void flash_attn(const float* __restrict__ Qm, const float* __restrict__ Km,
                const float* __restrict__ Vm, float* __restrict__ Om)
{
    __shared__ __align__(16) __nv_bfloat16 smarr[18432];
    __nv_bfloat16* sm = smarr;
    const int tid = threadIdx.x, lane = tid & 31, w = tid >> 5;
    const int qt = blockIdx.x, bh = blockIdx.y;
    const int b = bh >> 4, h = bh & 15;

    const float* qg  = Qm + ((long)(b*SEQ + qt*128))*DMODEL + h*64;
    const float* kg0 = Km + ((long)b*SEQ)*DMODEL + h*64;
    const float* vg0 = Vm + ((long)b*SEQ)*DMODEL + h*64;

    const uint32_t smb = (uint32_t)__cvta_generic_to_shared(sm);
    const float QSCALE = 0.125f * 1.4426950408889634f;   // (1/sqrt(64)) * log2(e)

    // ---- stage Q (hi at elem 0, lo at elem 9216), extract A frags, free smem
    #pragma unroll
    for (int r = 0; r < 8; r++) {
        int idx = tid + r*256;
        int row = idx >> 4, c4 = idx & 15;
        float4 vv = *(const float4*)(qg + (long)row*DMODEL + c4*4);
        vv.x *= QSCALE; vv.y *= QSCALE; vv.z *= QSCALE; vv.w *= QSCALE;
        __nv_bfloat16 h0,h1,h2,h3,e0,e1,e2,e3;
        split2(vv.x,h0,e0); split2(vv.y,h1,e1); split2(vv.z,h2,e2); split2(vv.w,h3,e3);
        *(uint2*)&sm[row*72 + c4*4]        = make_uint2(pack2(h0,h1), pack2(h2,h3));
        *(uint2*)&sm[9216 + row*72 + c4*4] = make_uint2(pack2(e0,e1), pack2(e2,e3));
    }
    __syncthreads();

    uint32_t qh[4][4], qlo[4][4];
    {
        const int a_row = w*16 + ((lane>>3)&1)*8 + (lane&7);
        const int a_k   = (lane>>4)*8;
        #pragma unroll
        for (int c = 0; c < 4; c++) {
            ldsm4(qh[c],  smb + (uint32_t)((a_row*72 + a_k + c*16)*2));
            ldsm4(qlo[c], smb + (uint32_t)((9216 + a_row*72 + a_k + c*16)*2));
        }
    }
    __syncthreads();

    // smem reuse: Kh@0, Kl@4608, Vh@9216, Vl@13824 (V transposed: [n=64][k=72])
    float o[8][4];
    #pragma unroll
    for (int i = 0; i < 8; i++)
        #pragma unroll
        for (int r = 0; r < 4; r++) o[i][r] = 0.f;
    float m0 = -1e30f, m1 = -1e30f, l0 = 0.f, l1 = 0.f;

    const int brow = (lane>>4)*8 + (lane&7);
    const int bk   = ((lane>>3)&1)*8;

    for (int kt = 0; kt < SEQ/64; kt++) {
        const float* kg = kg0 + (long)kt*64*DMODEL;
        const float* vg = vg0 + (long)kt*64*DMODEL;
        #pragma unroll
        for (int r = 0; r < 4; r++) {
            int idx = tid + r*256;
            int row = idx >> 4, c4 = idx & 15;
            float4 vv = *(const float4*)(kg + (long)row*DMODEL + c4*4);
            __nv_bfloat16 h0,h1,h2,h3,e0,e1,e2,e3;
            split2(vv.x,h0,e0); split2(vv.y,h1,e1); split2(vv.z,h2,e2); split2(vv.w,h3,e3);
            *(uint2*)&sm[row*72 + c4*4]        = make_uint2(pack2(h0,h1), pack2(h2,h3));
            *(uint2*)&sm[4608 + row*72 + c4*4] = make_uint2(pack2(e0,e1), pack2(e2,e3));
        }
        #pragma unroll
        for (int r = 0; r < 4; r++) {
            int idx = tid + r*256;
            int krow = idx >> 4, c4 = idx & 15;
            float4 vv = *(const float4*)(vg + (long)krow*DMODEL + c4*4);
            const float* vp = &vv.x;
            #pragma unroll
            for (int j = 0; j < 4; j++) {
                __nv_bfloat16 hh, ll;
                split2(vp[j], hh, ll);
                sm[9216  + (c4*4+j)*72 + krow] = hh;
                sm[13824 + (c4*4+j)*72 + krow] = ll;
            }
        }
        __syncthreads();

        // ---- S = Qhat K^T (bf16x3), 128x64 tile per CTA, 16x64 per warp
        float s[8][4];
        #pragma unroll
        for (int i = 0; i < 8; i++)
            #pragma unroll
            for (int r = 0; r < 4; r++) s[i][r] = 0.f;

        #pragma unroll
        for (int c = 0; c < 4; c++) {
            #pragma unroll
            for (int t = 0; t < 4; t++) {
                uint32_t bhF[4], blF[4];
                ldsm4(bhF, smb + (uint32_t)((       (t*16+brow)*72 + bk + c*16)*2));
                ldsm4(blF, smb + (uint32_t)((4608 + (t*16+brow)*72 + bk + c*16)*2));
                mma16816(s[2*t],   qh[c],  bhF);
                mma16816(s[2*t+1], qh[c],  bhF+2);
                mma16816(s[2*t],   qh[c],  blF);
                mma16816(s[2*t+1], qh[c],  blF+2);
                mma16816(s[2*t],   qlo[c], bhF);
                mma16816(s[2*t+1], qlo[c], bhF+2);
            }
        }

        // ---- online softmax (base-2)
        float mx0 = -1e30f, mx1 = -1e30f;
        #pragma unroll
        for (int t = 0; t < 8; t++) {
            mx0 = fmaxf(mx0, fmaxf(s[t][0], s[t][1]));
            mx1 = fmaxf(mx1, fmaxf(s[t][2], s[t][3]));
        }
        mx0 = fmaxf(mx0, __shfl_xor_sync(~0u, mx0, 1));
        mx0 = fmaxf(mx0, __shfl_xor_sync(~0u, mx0, 2));
        mx1 = fmaxf(mx1, __shfl_xor_sync(~0u, mx1, 1));
        mx1 = fmaxf(mx1, __shfl_xor_sync(~0u, mx1, 2));
        float mn0 = fmaxf(m0, mx0), mn1 = fmaxf(m1, mx1);
        float cr0 = exp2f_fast(m0 - mn0), cr1 = exp2f_fast(m1 - mn1);
        m0 = mn0; m1 = mn1;
        float s0 = 0.f, s1 = 0.f;
        #pragma unroll
        for (int t = 0; t < 8; t++) {
            s[t][0] = exp2f_fast(s[t][0] - m0); s0 += s[t][0];
            s[t][1] = exp2f_fast(s[t][1] - m0); s0 += s[t][1];
            s[t][2] = exp2f_fast(s[t][2] - m1); s1 += s[t][2];
            s[t][3] = exp2f_fast(s[t][3] - m1); s1 += s[t][3];
        }
        l0 = l0*cr0 + s0; l1 = l1*cr1 + s1;
        #pragma unroll
        for (int t = 0; t < 8; t++) {
            o[t][0] *= cr0; o[t][1] *= cr0; o[t][2] *= cr1; o[t][3] *= cr1;
        }

        // ---- O += P V (bf16x3; P repacked C-frag -> A-frag)
        #pragma unroll
        for (int c = 0; c < 4; c++) {
            __nv_bfloat16 hh[8], ll[8];
            split2(s[2*c][0],   hh[0], ll[0]); split2(s[2*c][1],   hh[1], ll[1]);
            split2(s[2*c][2],   hh[2], ll[2]); split2(s[2*c][3],   hh[3], ll[3]);
            split2(s[2*c+1][0], hh[4], ll[4]); split2(s[2*c+1][1], hh[5], ll[5]);
            split2(s[2*c+1][2], hh[6], ll[6]); split2(s[2*c+1][3], hh[7], ll[7]);
            uint32_t ph[4], pl[4];
            ph[0] = pack2(hh[0],hh[1]); ph[1] = pack2(hh[2],hh[3]);
            ph[2] = pack2(hh[4],hh[5]); ph[3] = pack2(hh[6],hh[7]);
            pl[0] = pack2(ll[0],ll[1]); pl[1] = pack2(ll[2],ll[3]);
            pl[2] = pack2(ll[4],ll[5]); pl[3] = pack2(ll[6],ll[7]);
            #pragma unroll
            for (int t = 0; t < 4; t++) {
                uint32_t vhF[4], vlF[4];
                ldsm4(vhF, smb + (uint32_t)((9216  + (t*16+brow)*72 + bk + c*16)*2));
                ldsm4(vlF, smb + (uint32_t)((13824 + (t*16+brow)*72 + bk + c*16)*2));
                mma16816(o[2*t],   ph, vhF);
                mma16816(o[2*t+1], ph, vhF+2);
                mma16816(o[2*t],   ph, vlF);
                mma16816(o[2*t+1], ph, vlF+2);
                mma16816(o[2*t],   pl, vhF);
                mma16816(o[2*t+1], pl, vhF+2);
            }
        }
        __syncthreads();
    }

    // ---- epilogue: finish row sums over the quad, normalize, store
    l0 += __shfl_xor_sync(~0u, l0, 1); l0 += __shfl_xor_sync(~0u, l0, 2);
    l1 += __shfl_xor_sync(~0u, l1, 1); l1 += __shfl_xor_sync(~0u, l1, 2);
    float inv0 = 1.f / l0, inv1 = 1.f / l1;
    float* og = Om + ((long)(b*SEQ + qt*128))*DMODEL + h*64;
    const int r0 = w*16 + (lane >> 2), r1 = r0 + 8;
    #pragma unroll
    for (int t = 0; t < 8; t++) {
        int col = t*8 + (lane & 3)*2;
        *(float2*)(og + (long)r0*DMODEL + col) = make_float2(o[t][0]*inv0, o[t][1]*inv0);
        *(float2*)(og + (long)r1*DMODEL + col) = make_float2(o[t][2]*inv1, o[t][3]*inv1);
    }
}

// ---------------- depthwise conv (K=3, pad=1) ---------------------------------
__global__ __launch_bounds__(256)
void dwconv_k(const float* __restrict__ x, const float* __restrict__ w,
              const float* __restrict__ b, float* __restrict__ out)
{
    long i = (long)blockIdx.x*256 + threadIdx.x;
    int  c  = (int)(i & (DMODEL-1));
    long sl = i >> 10;
    int  s  = (int)(sl & (SEQ-1));
    float w0 = w[c*3+0], w1 = w[c*3+1], w2 = w[c*3+2];
    float acc = b[c] + w1 * x[i];
    if (s > 0)      acc += w0 * x[i - DMODEL];
    if (s < SEQ-1)  acc += w2 * x[i + DMODEL];
    out[i] = acc;
}

// ---------------- launcher ----------------------------------------------------
extern "C" void kernel_launch(void* const* d_in, const int* in_sizes, int n_in,
                              void* d_out, int out_size)
{
    const float* x    = (const float*)d_in[0];
    const float* wq   = (const float*)d_in[1];
    const float* bq   = (const float*)d_in[2];
    const float* wk   = (const float*)d_in[3];
    const float* bk   = (const float*)d_in[4];
    const float* wv   = (const float*)d_in[5];
    const float* bv   = (const float*)d_in[6];
    const float* wo   = (const float*)d_in[7];
    const float* bo   = (const float*)d_in[8];
    const float* dw_w = (const float*)d_in[9];
    const float* dw_b = (const float*)d_in[10];
    const float* pw_w = (const float*)d_in[11];
    const float* pw_b = (const float*)d_in[12];
    const float* fu_w = (const float*)d_in[13];
    const float* fu_b = (const float*)d_in[14];
    float* out = (float*)d_out;

    float *q,*k,*v,*attn,*dw,*fused;
    cudaGetSymbolAddress((void**)&q,     g_q);
    cudaGetSymbolAddress((void**)&k,     g_k);
    cudaGetSymbolAddress((void**)&v,     g_v);
    cudaGetSymbolAddress((void**)&attn,  g_attn);
    cudaGetSymbolAddress((void**)&dw,    g_dw);
    cudaGetSymbolAddress((void**)&fused, g_fused);

    const dim3 thr(256);

    // QKV projections in one launch (z selects weight/bias/output)
    qkv_gemm<<<dim3(DMODEL/128, MTOT/128, 3), thr>>>(x, wq, wk, wv, bq, bk, bv, q, k, v);

    // conv branch depthwise
    dwconv_k<<<(MTOT*DMODEL)/256, thr>>>(x, dw_w, dw_b, dw);

    // fused flash attention (scores + softmax + PV)
    flash_attn<<<dim3(SEQ/128, BBATCH*NH), thr>>>(q, k, v, attn);

    // pointwise+GELU (z=0) and output projection (z=1) into fused halves
    pair_gemm<<<dim3(DMODEL/128, MTOT/128, 2), thr>>>(dw, attn, pw_w, wo, pw_b, bo,
                                                      fused + DMODEL, fused);

    // fusion GEMM
    fusion_gemm<<<dim3(DMODEL/128, MTOT/128, 1), thr>>>(fused, fu_w, fu_b, out);
}